// round 2
// baseline (speedup 1.0000x reference)
#include <cuda_runtime.h>

#define NEG (-1e30f)

// dims
#define BB   8
#define NN   196
#define DD   128
#define DFF  256
#define PD   256
#define MM   (BB*NN)   // 1568
#define CC   1000

// -------- scratch (device globals; no allocation allowed) --------
__device__ __align__(128) float g_patches[MM * PD];   // 1.6 MB
__device__ __align__(128) float g_h[MM * DD];
__device__ __align__(128) float g_q[MM * DD];
__device__ __align__(128) float g_k[MM * DD];
__device__ __align__(128) float g_v[MM * DD];
__device__ __align__(128) float g_t[MM * DFF];
__device__ __align__(128) float g_mx[MM];
__device__ __align__(128) float g_pooled[BB * DD];

// ---------------------------------------------------------------
// patchify: (8,224,224) -> (1568,256)
// ---------------------------------------------------------------
__global__ void patchify_kernel(const float* __restrict__ x) {
    int g = blockIdx.x * 256 + threadIdx.x;     // 100352 threads, 1 float4 each
    int m = g >> 6;                              // row (b,n)
    int j = (g & 63) * 4;                        // patch-dim offset
    int b = m / NN, n = m % NN;
    int gy = n / 14, gx = n % 14;
    int py = j >> 4, px = j & 15;
    float4 v = *(const float4*)&x[(b * 224 + gy * 16 + py) * 224 + gx * 16 + px];
    *(float4*)&g_patches[m * PD + j] = v;
}

// ---------------------------------------------------------------
// tropical GEMM core: acc[16 rows] x 128 cols, K-chunked by 32
// X row-major [*, K], W row-major [128 (this block's cols), K]
// ---------------------------------------------------------------
template<int K>
__device__ __forceinline__ void trop_accumulate(
    const float* __restrict__ X, const float* __restrict__ W,
    int m0, int t, float acc[16], float sx[][32], float sw[][36])
{
#pragma unroll
    for (int m = 0; m < 16; m++) acc[m] = NEG;

    int row = t >> 3;            // 0..15
    int kp  = (t & 7) * 4;       // 0,4,...,28

    for (int k0 = 0; k0 < K; k0 += 32) {
        // stage X tile [16][32]
        *(float4*)&sx[row][kp] = *(const float4*)&X[(m0 + row) * K + k0 + kp];
        // stage W tile [128][32] (+pad 36 for conflict-free column reads)
#pragma unroll
        for (int p = 0; p < 8; p++) {
            int i = p * 16 + row;
            *(float4*)&sw[i][kp] = *(const float4*)&W[i * K + k0 + kp];
        }
        __syncthreads();
#pragma unroll
        for (int kk = 0; kk < 32; kk += 4) {
            float4 wv = *(const float4*)&sw[t][kk];
#pragma unroll
            for (int m = 0; m < 16; m++) {
                float4 xv = *(const float4*)&sx[m][kk];
                float a0 = fmaxf(xv.x + wv.x, xv.y + wv.y);
                float a1 = fmaxf(xv.z + wv.z, xv.w + wv.w);
                acc[m] = fmaxf(acc[m], fmaxf(a0, a1));
            }
        }
        __syncthreads();
    }
}

// ---------------------------------------------------------------
// embed: h = trop_mm(patches, embed_W) + pos
// grid (98), block 128
// ---------------------------------------------------------------
__global__ void embed_kernel(const float* __restrict__ W, const float* __restrict__ pos) {
    __shared__ float sx[16][32];
    __shared__ float sw[128][36];
    int t = threadIdx.x, m0 = blockIdx.x * 16;
    float acc[16];
    trop_accumulate<PD>(g_patches, W, m0, t, acc, sx, sw);
#pragma unroll
    for (int mi = 0; mi < 16; mi++) {
        int m = m0 + mi;
        g_h[m * DD + t] = acc[mi] + pos[(m % NN) * DD + t];
    }
}

// ---------------------------------------------------------------
// rowmax of g_h -> g_mx  (one warp per row)
// grid (196), block 256
// ---------------------------------------------------------------
__global__ void rowmax_kernel() {
    int w = (blockIdx.x * blockDim.x + threadIdx.x) >> 5;
    int lane = threadIdx.x & 31;
    const float* r = g_h + w * DD;
    float v = fmaxf(fmaxf(r[lane], r[lane + 32]), fmaxf(r[lane + 64], r[lane + 96]));
#pragma unroll
    for (int o = 16; o; o >>= 1) v = fmaxf(v, __shfl_xor_sync(~0u, v, o));
    if (lane == 0) g_mx[w] = v;
}

// ---------------------------------------------------------------
// qkv: {q,k,v} = trop_mm(h, W) - mx   (pnorm folded into epilogue)
// grid (98, 3), block 128
// ---------------------------------------------------------------
__global__ void qkv_kernel(const float* __restrict__ qW, const float* __restrict__ kW,
                           const float* __restrict__ vW) {
    __shared__ float sx[16][32];
    __shared__ float sw[128][36];
    int t = threadIdx.x, m0 = blockIdx.x * 16;
    const float* W = (blockIdx.y == 0) ? qW : (blockIdx.y == 1) ? kW : vW;
    float* O = (blockIdx.y == 0) ? g_q : (blockIdx.y == 1) ? g_k : g_v;
    float acc[16];
    trop_accumulate<DD>(g_h, W, m0, t, acc, sx, sw);
#pragma unroll
    for (int mi = 0; mi < 16; mi++) {
        int m = m0 + mi;
        O[m * DD + t] = acc[mi] - g_mx[m];
    }
}

// ---------------------------------------------------------------
// fused attention:  s_ij = max_d(q+k);  U = max_j(s + v);
// a = U - max_d U  (score norm cancels);  h = max(h, a)
// grid (25 i-tiles, 8 batches), block 128 = 8 i-rows x 16 lanes (8 d each)
// ---------------------------------------------------------------
__global__ void attn_kernel() {
    __shared__ float ks[8][128];
    __shared__ float vs[8][128];
    int t = threadIdx.x;
    int b = blockIdx.y;
    int i0 = blockIdx.x * 8;
    int il = t >> 4;            // which i row
    int d0 = (t & 15) * 8;      // this lane's d chunk
    int i = i0 + il;
    bool ivalid = (i < NN);

    float qr[8];
    {
        const float* qp = g_q + (b * NN + (ivalid ? i : 0)) * DD + d0;
#pragma unroll
        for (int d = 0; d < 8; d++) qr[d] = ivalid ? qp[d] : NEG;
    }
    float U[8];
#pragma unroll
    for (int d = 0; d < 8; d++) U[d] = NEG;

    int ljj = t >> 4;
    int ldp = (t & 15) * 8;

    for (int j0 = 0; j0 < NN; j0 += 8) {
        int j = j0 + ljj;
        if (j < NN) {
            const float* kp_ = g_k + (b * NN + j) * DD + ldp;
            const float* vp_ = g_v + (b * NN + j) * DD + ldp;
            *(float4*)&ks[ljj][ldp]     = *(const float4*)&kp_[0];
            *(float4*)&ks[ljj][ldp + 4] = *(const float4*)&kp_[4];
            *(float4*)&vs[ljj][ldp]     = *(const float4*)&vp_[0];
            *(float4*)&vs[ljj][ldp + 4] = *(const float4*)&vp_[4];
        } else {
            float4 nv = make_float4(NEG, NEG, NEG, NEG);
            *(float4*)&ks[ljj][ldp] = nv; *(float4*)&ks[ljj][ldp + 4] = nv;
            *(float4*)&vs[ljj][ldp] = nv; *(float4*)&vs[ljj][ldp + 4] = nv;
        }
        __syncthreads();
#pragma unroll
        for (int jj = 0; jj < 8; jj++) {
            float4 k0v = *(const float4*)&ks[jj][d0];
            float4 k1v = *(const float4*)&ks[jj][d0 + 4];
            float s = fmaxf(fmaxf(fmaxf(qr[0] + k0v.x, qr[1] + k0v.y),
                                  fmaxf(qr[2] + k0v.z, qr[3] + k0v.w)),
                            fmaxf(fmaxf(qr[4] + k1v.x, qr[5] + k1v.y),
                                  fmaxf(qr[6] + k1v.z, qr[7] + k1v.w)));
            s = fmaxf(s, __shfl_xor_sync(~0u, s, 8));
            s = fmaxf(s, __shfl_xor_sync(~0u, s, 4));
            s = fmaxf(s, __shfl_xor_sync(~0u, s, 2));
            s = fmaxf(s, __shfl_xor_sync(~0u, s, 1));
            float4 v0v = *(const float4*)&vs[jj][d0];
            float4 v1v = *(const float4*)&vs[jj][d0 + 4];
            U[0] = fmaxf(U[0], s + v0v.x); U[1] = fmaxf(U[1], s + v0v.y);
            U[2] = fmaxf(U[2], s + v0v.z); U[3] = fmaxf(U[3], s + v0v.w);
            U[4] = fmaxf(U[4], s + v1v.x); U[5] = fmaxf(U[5], s + v1v.y);
            U[6] = fmaxf(U[6], s + v1v.z); U[7] = fmaxf(U[7], s + v1v.w);
        }
        __syncthreads();
    }

    float um = NEG;
#pragma unroll
    for (int d = 0; d < 8; d++) um = fmaxf(um, U[d]);
    um = fmaxf(um, __shfl_xor_sync(~0u, um, 8));
    um = fmaxf(um, __shfl_xor_sync(~0u, um, 4));
    um = fmaxf(um, __shfl_xor_sync(~0u, um, 2));
    um = fmaxf(um, __shfl_xor_sync(~0u, um, 1));

    if (ivalid) {
        float* hp = g_h + (b * NN + i) * DD + d0;
#pragma unroll
        for (int d = 0; d < 8; d++) hp[d] = fmaxf(hp[d], U[d] - um);
    }
}

// ---------------------------------------------------------------
// ff1: t = max(trop_mm(h, f1W) - mx, tau)
// grid (98, 2), block 128
// ---------------------------------------------------------------
__global__ void ff1_kernel(const float* __restrict__ W, const float* __restrict__ tau) {
    __shared__ float sx[16][32];
    __shared__ float sw[128][36];
    int t = threadIdx.x, m0 = blockIdx.x * 16;
    const float* Ws = W + blockIdx.y * 128 * DD;
    float acc[16];
    trop_accumulate<DD>(g_h, Ws, m0, t, acc, sx, sw);
    float tv = tau[0];
#pragma unroll
    for (int mi = 0; mi < 16; mi++) {
        int m = m0 + mi;
        g_t[m * DFF + blockIdx.y * 128 + t] = fmaxf(acc[mi] - g_mx[m], tv);
    }
}

// ---------------------------------------------------------------
// ff2: u = trop_mm(t, f2W); h = max(h, u - rowmax_d(u))
// grid (98), block 128
// ---------------------------------------------------------------
__global__ void ff2_kernel(const float* __restrict__ W) {
    __shared__ float sx[16][32];
    __shared__ float sw[128][36];
    __shared__ float red[4][16];
    int t = threadIdx.x, m0 = blockIdx.x * 16;
    float acc[16];
    trop_accumulate<DFF>(g_t, W, m0, t, acc, sx, sw);

    int warp = t >> 5, lane = t & 31;
#pragma unroll
    for (int m = 0; m < 16; m++) {
        float v = acc[m];
#pragma unroll
        for (int o = 16; o; o >>= 1) v = fmaxf(v, __shfl_xor_sync(~0u, v, o));
        if (lane == 0) red[warp][m] = v;
    }
    __syncthreads();
#pragma unroll
    for (int m = 0; m < 16; m++) {
        float rm = fmaxf(fmaxf(red[0][m], red[1][m]), fmaxf(red[2][m], red[3][m]));
        int mm = m0 + m;
        float nv = acc[m] - rm;
        g_h[mm * DD + t] = fmaxf(g_h[mm * DD + t], nv);
    }
}

// ---------------------------------------------------------------
// pool: pooled[b][d] = max_n h[b][n][d]
// grid (8), block 128
// ---------------------------------------------------------------
__global__ void pool_kernel() {
    int b = blockIdx.x, d = threadIdx.x;
    const float* hp = g_h + b * NN * DD + d;
    float v = NEG;
#pragma unroll 4
    for (int n = 0; n < NN; n++) v = fmaxf(v, hp[n * DD]);
    g_pooled[b * DD + d] = v;
}

// ---------------------------------------------------------------
// head: out[b][c] = (max_d pooled[b][d] + W[c][d]) * logit_scale
// grid (8, 63), block 128 = 16 c x 8 lanes (16 d each)
// ---------------------------------------------------------------
__global__ void head_kernel(const float* __restrict__ W, const float* __restrict__ ls,
                            float* __restrict__ out) {
    int t = threadIdx.x;
    int b = blockIdx.x;
    int c = blockIdx.y * 16 + (t >> 3);
    int dp = (t & 7) * 16;
    float acc = NEG;
    if (c < CC) {
        const float* p = g_pooled + b * DD + dp;
        const float* w = W + c * DD + dp;
#pragma unroll
        for (int d = 0; d < 16; d += 4) {
            float4 wv = *(const float4*)&w[d];
            float4 pv = *(const float4*)&p[d];
            acc = fmaxf(acc, fmaxf(fmaxf(pv.x + wv.x, pv.y + wv.y),
                                   fmaxf(pv.z + wv.z, pv.w + wv.w)));
        }
    }
#pragma unroll
    for (int o = 4; o; o >>= 1) acc = fmaxf(acc, __shfl_xor_sync(~0u, acc, o));
    if ((t & 7) == 0 && c < CC) out[b * CC + c] = acc * ls[0];
}

// ---------------------------------------------------------------
extern "C" void kernel_launch(void* const* d_in, const int* in_sizes, int n_in,
                              void* d_out, int out_size) {
    const float* x      = (const float*)d_in[0];
    const float* embedW = (const float*)d_in[1];
    const float* pos    = (const float*)d_in[2];
    const float* qW[2]  = {(const float*)d_in[3],  (const float*)d_in[9]};
    const float* kW[2]  = {(const float*)d_in[4],  (const float*)d_in[10]};
    const float* vW[2]  = {(const float*)d_in[5],  (const float*)d_in[11]};
    const float* f1W[2] = {(const float*)d_in[6],  (const float*)d_in[12]};
    const float* f2W[2] = {(const float*)d_in[7],  (const float*)d_in[13]};
    const float* tau[2] = {(const float*)d_in[8],  (const float*)d_in[14]};
    const float* headW  = (const float*)d_in[15];
    const float* ls     = (const float*)d_in[16];
    float* out = (float*)d_out;

    patchify_kernel<<<392, 256>>>(x);
    embed_kernel<<<98, 128>>>(embedW, pos);

    for (int l = 0; l < 2; l++) {
        rowmax_kernel<<<196, 256>>>();
        qkv_kernel<<<dim3(98, 3), 128>>>(qW[l], kW[l], vW[l]);
        attn_kernel<<<dim3(25, 8), 128>>>();
        rowmax_kernel<<<196, 256>>>();
        ff1_kernel<<<dim3(98, 2), 128>>>(f1W[l], tau[l]);
        ff2_kernel<<<98, 128>>>(f2W[l]);
    }

    pool_kernel<<<8, 128>>>();
    head_kernel<<<dim3(8, 63), 128>>>(headW, ls, out);
}

// round 4
// speedup vs baseline: 1.5629x; 1.5629x over previous
#include <cuda_runtime.h>

#define NEG (-1e30f)

// dims
#define BB   8
#define NN   196
#define DD   128
#define DFF  256
#define PD   256
#define MM   (BB*NN)   // 1568
#define CC   1000

// -------- scratch (device globals; no allocation allowed) --------
__device__ __align__(128) float g_h[MM * DD];
__device__ __align__(128) float g_q[MM * DD];
__device__ __align__(128) float g_k[MM * DD];
__device__ __align__(128) float g_v[MM * DD];
__device__ __align__(128) float g_t[MM * DFF];
__device__ __align__(128) float g_mx[MM];

// ---------------------------------------------------------------
// X-tile loaders (stage ROWS x 64 k-chunk into shared)
// ---------------------------------------------------------------
struct XRow {
    const float* X; int m0; int ld;
    __device__ __forceinline__ void operator()(float (*sx)[64], int k0, int t) const {
        int row = t >> 4, kp = (t & 15) * 4;
        *(float4*)&sx[row][kp] = *(const float4*)&X[(m0 + row) * ld + k0 + kp];
    }
};
// patchify-on-the-fly: x is (8,224,224); row m -> (b, n); k index j -> (py, px)
struct XPatch {
    const float* x; int m0;
    __device__ __forceinline__ void operator()(float (*sx)[64], int k0, int t) const {
        int row = t >> 4, kp = (t & 15) * 4;
        int m = m0 + row;
        int b = m / NN, n = m % NN;
        int gy = n / 14, gx = n % 14;
        int j = k0 + kp;
        int py = j >> 4, px = j & 15;     // px multiple of 4 -> float4 ok
        *(float4*)&sx[row][kp] =
            *(const float4*)&x[(b * 224 + gy * 16 + py) * 224 + gx * 16 + px];
    }
};

// ---------------------------------------------------------------
// tropical GEMM core: ROWS rows x 128 cols per block (128 threads),
// K chunked by 64.  W row-major [128 cols, K]. Thread t owns col t.
// sw pad 68 (68 mod 32 == 4): LDS.128 phases conflict-free.
// ---------------------------------------------------------------
template<int ROWS, int K, class XL>
__device__ __forceinline__ void trop_core(const XL& xl, const float* __restrict__ W,
                                          float acc[ROWS],
                                          float (*sx)[64], float (*sw)[68])
{
    int t = threadIdx.x;
#pragma unroll
    for (int m = 0; m < ROWS; m++) acc[m] = NEG;

    for (int k0 = 0; k0 < K; k0 += 64) {
        if (t < ROWS * 16) xl(sx, k0, t);
#pragma unroll
        for (int p = 0; p < 16; p++) {          // 128 rows x 16 float4
            int l = p * 128 + t;
            int i = l >> 4, kp = (l & 15) * 4;
            *(float4*)&sw[i][kp] = *(const float4*)&W[i * K + k0 + kp];
        }
        __syncthreads();
#pragma unroll
        for (int kk = 0; kk < 64; kk += 4) {
            float4 wv = *(const float4*)&sw[t][kk];
#pragma unroll
            for (int m = 0; m < ROWS; m++) {
                float4 xv = *(const float4*)&sx[m][kk];   // warp broadcast
                float a0 = fmaxf(xv.x + wv.x, xv.y + wv.y);
                float a1 = fmaxf(xv.z + wv.z, xv.w + wv.w);
                acc[m] = fmaxf(acc[m], fmaxf(a0, a1));
            }
        }
        __syncthreads();
    }
}

// block-wide (128 thr) rowmax of ROWS register values -> g_mx[m0+..]
template<int ROWS>
__device__ __forceinline__ void rowmax_epilogue(const float acc[ROWS], int m0,
                                                float (*red)[ROWS])
{
    int t = threadIdx.x, warp = t >> 5, lane = t & 31;
#pragma unroll
    for (int m = 0; m < ROWS; m++) {
        float v = acc[m];
#pragma unroll
        for (int o = 16; o; o >>= 1) v = fmaxf(v, __shfl_xor_sync(~0u, v, o));
        if (lane == 0) red[warp][m] = v;
    }
    __syncthreads();
    if (t < ROWS)
        g_mx[m0 + t] = fmaxf(fmaxf(red[0][t], red[1][t]),
                             fmaxf(red[2][t], red[3][t]));
}

// ---------------------------------------------------------------
// embed: h = trop_mm(patchify(x), embed_W) + pos ; g_mx = rowmax(h)
// grid 392, block 128 (4 rows/block)
// ---------------------------------------------------------------
__global__ void embed_kernel(const float* __restrict__ x, const float* __restrict__ W,
                             const float* __restrict__ pos) {
    __shared__ float sx[4][64];
    __shared__ float sw[128][68];
    __shared__ float red[4][4];
    int t = threadIdx.x, m0 = blockIdx.x * 4;
    float acc[4];
    XPatch xl{x, m0};
    trop_core<4, PD>(xl, W, acc, sx, sw);
#pragma unroll
    for (int m = 0; m < 4; m++) {
        acc[m] += pos[((m0 + m) % NN) * DD + t];
        g_h[(m0 + m) * DD + t] = acc[m];
    }
    rowmax_epilogue<4>(acc, m0, red);
}

// ---------------------------------------------------------------
// qkv: {q,k,v} = trop_mm(h, W) - mx
// grid (196,3), block 128 (8 rows/block)
// ---------------------------------------------------------------
__global__ void qkv_kernel(const float* __restrict__ qW, const float* __restrict__ kW,
                           const float* __restrict__ vW) {
    __shared__ float sx[8][64];
    __shared__ float sw[128][68];
    int t = threadIdx.x, m0 = blockIdx.x * 8;
    const float* W = (blockIdx.y == 0) ? qW : (blockIdx.y == 1) ? kW : vW;
    float* O = (blockIdx.y == 0) ? g_q : (blockIdx.y == 1) ? g_k : g_v;
    float acc[8];
    XRow xl{g_h, m0, DD};
    trop_core<8, DD>(xl, W, acc, sx, sw);
#pragma unroll
    for (int m = 0; m < 8; m++)
        O[(m0 + m) * DD + t] = acc[m] - g_mx[m0 + m];
}

// ---------------------------------------------------------------
// fused attention + residual + rowmax epilogue
// grid (25, 8), block 256 = 8 i-rows x 32 lanes (4 d each)
// ---------------------------------------------------------------
__global__ void attn_kernel() {
    __shared__ float ks[8][128];
    __shared__ float vs[8][128];
    int t = threadIdx.x;
    int b = blockIdx.y;
    int il = t >> 5, lane = t & 31;
    int d0 = lane * 4;
    int i = blockIdx.x * 8 + il;
    bool iv = (i < NN);

    const float* qp = g_q + (b * NN + (iv ? i : 0)) * DD + d0;
    float q0 = iv ? qp[0] : NEG, q1 = iv ? qp[1] : NEG;
    float q2 = iv ? qp[2] : NEG, q3 = iv ? qp[3] : NEG;
    float U0 = NEG, U1 = NEG, U2 = NEG, U3 = NEG;

    for (int j0 = 0; j0 < NN; j0 += 8) {
        int j = j0 + il;
        if (j < NN) {
            const float* kp_ = g_k + (b * NN + j) * DD + d0;
            const float* vp_ = g_v + (b * NN + j) * DD + d0;
            *(float4*)&ks[il][d0] = *(const float4*)&kp_[0];
            *(float4*)&vs[il][d0] = *(const float4*)&vp_[0];
        } else {
            float4 nv = make_float4(NEG, NEG, NEG, NEG);
            *(float4*)&ks[il][d0] = nv;
            *(float4*)&vs[il][d0] = nv;
        }
        __syncthreads();
#pragma unroll
        for (int jj = 0; jj < 8; jj++) {
            float4 kv = *(const float4*)&ks[jj][d0];
            float s = fmaxf(fmaxf(q0 + kv.x, q1 + kv.y),
                            fmaxf(q2 + kv.z, q3 + kv.w));
#pragma unroll
            for (int o = 16; o; o >>= 1) s = fmaxf(s, __shfl_xor_sync(~0u, s, o));
            float4 vv = *(const float4*)&vs[jj][d0];
            U0 = fmaxf(U0, s + vv.x); U1 = fmaxf(U1, s + vv.y);
            U2 = fmaxf(U2, s + vv.z); U3 = fmaxf(U3, s + vv.w);
        }
        __syncthreads();
    }

    float um = fmaxf(fmaxf(U0, U1), fmaxf(U2, U3));
#pragma unroll
    for (int o = 16; o; o >>= 1) um = fmaxf(um, __shfl_xor_sync(~0u, um, o));

    if (iv) {
        float* hp = g_h + (b * NN + i) * DD + d0;
        float h0 = fmaxf(hp[0], U0 - um), h1 = fmaxf(hp[1], U1 - um);
        float h2 = fmaxf(hp[2], U2 - um), h3 = fmaxf(hp[3], U3 - um);
        hp[0] = h0; hp[1] = h1; hp[2] = h2; hp[3] = h3;
        float v = fmaxf(fmaxf(h0, h1), fmaxf(h2, h3));
#pragma unroll
        for (int o = 16; o; o >>= 1) v = fmaxf(v, __shfl_xor_sync(~0u, v, o));
        if (lane == 0) g_mx[b * NN + i] = v;
    }
}

// ---------------------------------------------------------------
// ff1: t = max(trop_mm(h, f1W) - mx, tau)
// grid (196, 2), block 128 (8 rows/block)
// ---------------------------------------------------------------
__global__ void ff1_kernel(const float* __restrict__ W, const float* __restrict__ tau) {
    __shared__ float sx[8][64];
    __shared__ float sw[128][68];
    int t = threadIdx.x, m0 = blockIdx.x * 8;
    float acc[8];
    XRow xl{g_h, m0, DD};
    trop_core<8, DD>(xl, W + blockIdx.y * 128 * DD, acc, sx, sw);
    float tv = tau[0];
#pragma unroll
    for (int m = 0; m < 8; m++)
        g_t[(m0 + m) * DFF + blockIdx.y * 128 + t] = fmaxf(acc[m] - g_mx[m0 + m], tv);
}

// ---------------------------------------------------------------
// ff2: u = trop_mm(t, f2W); h = max(h, u - rowmax(u)); g_mx = rowmax(h)
// grid 392, block 128 (4 rows/block)
// ---------------------------------------------------------------
__global__ void ff2_kernel(const float* __restrict__ W) {
    __shared__ float sx[4][64];
    __shared__ float sw[128][68];
    __shared__ float red[4][4];
    int t = threadIdx.x, m0 = blockIdx.x * 4;
    float acc[4];
    XRow xl{g_t, m0, DFF};
    trop_core<4, DFF>(xl, W, acc, sx, sw);

    int warp = t >> 5, lane = t & 31;
#pragma unroll
    for (int m = 0; m < 4; m++) {
        float v = acc[m];
#pragma unroll
        for (int o = 16; o; o >>= 1) v = fmaxf(v, __shfl_xor_sync(~0u, v, o));
        if (lane == 0) red[warp][m] = v;
    }
    __syncthreads();
    float hn[4];
#pragma unroll
    for (int m = 0; m < 4; m++) {
        float rm = fmaxf(fmaxf(red[0][m], red[1][m]), fmaxf(red[2][m], red[3][m]));
        hn[m] = fmaxf(g_h[(m0 + m) * DD + t], acc[m] - rm);
        g_h[(m0 + m) * DD + t] = hn[m];
    }
    __syncthreads();
    rowmax_epilogue<4>(hn, m0, red);
}

// ---------------------------------------------------------------
// head with fused tropical global pool
// grid (8, 63), block 128 = 16 c-rows x 8 lanes (16 d each)
// ---------------------------------------------------------------
__global__ void head_kernel(const float* __restrict__ W, const float* __restrict__ ls,
                            float* __restrict__ out) {
    __shared__ float sp[128];
    int t = threadIdx.x, b = blockIdx.x;
    const float* hp = g_h + b * NN * DD + t;
    float v0 = NEG, v1 = NEG, v2 = NEG, v3 = NEG;
    for (int n = 0; n < NN; n += 4) {
        v0 = fmaxf(v0, hp[n * DD]);
        v1 = fmaxf(v1, hp[(n + 1) * DD]);
        v2 = fmaxf(v2, hp[(n + 2) * DD]);
        v3 = fmaxf(v3, hp[(n + 3) * DD]);
    }
    sp[t] = fmaxf(fmaxf(v0, v1), fmaxf(v2, v3));
    __syncthreads();

    int c = blockIdx.y * 16 + (t >> 3);
    int dp = (t & 7) * 16;
    float acc = NEG;
    if (c < CC) {
        const float* w = W + c * DD + dp;
#pragma unroll
        for (int d = 0; d < 16; d += 4) {
            float4 wv = *(const float4*)&w[d];
            acc = fmaxf(acc, fmaxf(fmaxf(sp[dp + d] + wv.x, sp[dp + d + 1] + wv.y),
                                   fmaxf(sp[dp + d + 2] + wv.z, sp[dp + d + 3] + wv.w)));
        }
    }
#pragma unroll
    for (int o = 4; o; o >>= 1) acc = fmaxf(acc, __shfl_xor_sync(~0u, acc, o));
    if ((t & 7) == 0 && c < CC) out[b * CC + c] = acc * ls[0];
}

// ---------------------------------------------------------------
extern "C" void kernel_launch(void* const* d_in, const int* in_sizes, int n_in,
                              void* d_out, int out_size) {
    const float* x      = (const float*)d_in[0];
    const float* embedW = (const float*)d_in[1];
    const float* pos    = (const float*)d_in[2];
    const float* qW[2]  = {(const float*)d_in[3],  (const float*)d_in[9]};
    const float* kW[2]  = {(const float*)d_in[4],  (const float*)d_in[10]};
    const float* vW[2]  = {(const float*)d_in[5],  (const float*)d_in[11]};
    const float* f1W[2] = {(const float*)d_in[6],  (const float*)d_in[12]};
    const float* f2W[2] = {(const float*)d_in[7],  (const float*)d_in[13]};
    const float* tau[2] = {(const float*)d_in[8],  (const float*)d_in[14]};
    const float* headW  = (const float*)d_in[15];
    const float* ls     = (const float*)d_in[16];
    float* out = (float*)d_out;

    embed_kernel<<<MM / 4, 128>>>(x, embedW, pos);

    for (int l = 0; l < 2; l++) {
        qkv_kernel<<<dim3(MM / 8, 3), 128>>>(qW[l], kW[l], vW[l]);
        attn_kernel<<<dim3(25, BB), 256>>>();
        ff1_kernel<<<dim3(MM / 8, 2), 128>>>(f1W[l], tau[l]);
        ff2_kernel<<<MM / 4, 128>>>(f2W[l]);
    }

    head_kernel<<<dim3(BB, 63), 128>>>(headW, ls, out);
}

// round 5
// speedup vs baseline: 1.6106x; 1.0305x over previous
#include <cuda_runtime.h>

#define NEG (-1e30f)

// dims
#define BB   8
#define NN   196
#define DD   128
#define DFF  256
#define PD   256
#define MM   (BB*NN)   // 1568
#define CC   1000

// -------- scratch (device globals; no allocation allowed) --------
__device__ __align__(128) float g_h[MM * DD];
__device__ __align__(128) float g_q[MM * DD];
__device__ __align__(128) float g_k[MM * DD];
__device__ __align__(128) float g_v[MM * DD];
__device__ __align__(128) float g_t[MM * DFF];
__device__ __align__(128) float g_mx[MM];

// ---------------------------------------------------------------
// X-tile loaders (stage ROWS x 64 k-chunk into shared, t < ROWS*16)
// ---------------------------------------------------------------
struct XRow {
    const float* X; int m0; int ld;
    __device__ __forceinline__ void operator()(float (*sx)[68], int k0, int t) const {
        int row = t >> 4, kp = (t & 15) * 4;
        *(float4*)&sx[row][kp] = *(const float4*)&X[(m0 + row) * ld + k0 + kp];
    }
};
// patchify-on-the-fly: x is (8,224,224); row m -> (b,n); k index j -> (py,px)
struct XPatch {
    const float* x; int m0;
    __device__ __forceinline__ void operator()(float (*sx)[68], int k0, int t) const {
        int row = t >> 4, kp = (t & 15) * 4;
        int m = m0 + row;
        int b = m / NN, n = m % NN;
        int gy = n / 14, gx = n % 14;
        int j = k0 + kp;
        int py = j >> 4, px = j & 15;
        *(float4*)&sx[row][kp] =
            *(const float4*)&x[(b * 224 + gy * 16 + py) * 224 + gx * 16 + px];
    }
};

// ---------------------------------------------------------------
// K-split tropical GEMM core. Block = 256 threads: col c = t&127,
// K-group g = t>>7 handles kk in [g*32, g*32+32) of each 64-chunk.
// Output tile: ROWS x 128 cols. W row-major [128 cols][K].
// ---------------------------------------------------------------
template<int ROWS, int K, class XL>
__device__ __forceinline__ void trop_core(const XL& xl, const float* __restrict__ W,
                                          float acc[ROWS],
                                          float (*sx)[68], float (*sw)[68])
{
    int t = threadIdx.x;
    int c = t & 127, kbase = (t >> 7) * 32;
#pragma unroll
    for (int m = 0; m < ROWS; m++) acc[m] = NEG;

    for (int k0 = 0; k0 < K; k0 += 64) {
        if (t < ROWS * 16) xl(sx, k0, t);
#pragma unroll
        for (int p = 0; p < 8; p++) {        // 128 rows x 16 float4 / 256 thr
            int l = p * 256 + t;
            int i = l >> 4, kp = (l & 15) * 4;
            *(float4*)&sw[i][kp] = *(const float4*)&W[i * K + k0 + kp];
        }
        __syncthreads();
#pragma unroll
        for (int kk = 0; kk < 32; kk += 4) {
            float4 wv = *(const float4*)&sw[c][kbase + kk];
#pragma unroll
            for (int m = 0; m < ROWS; m++) {
                float4 xv = *(const float4*)&sx[m][kbase + kk];   // broadcast
                float a0 = fmaxf(xv.x + wv.x, xv.y + wv.y);
                float a1 = fmaxf(xv.z + wv.z, xv.w + wv.w);
                acc[m] = fmaxf(acc[m], fmaxf(a0, a1));
            }
        }
        __syncthreads();
    }
}

// combine the two K-groups: after this, group 0 (t<128) holds the result
template<int ROWS>
__device__ __forceinline__ void combine(float acc[ROWS], float (*sc)[128]) {
    int t = threadIdx.x, c = t & 127;
    if (t >= 128) {
#pragma unroll
        for (int m = 0; m < ROWS; m++) sc[m][c] = acc[m];
    }
    __syncthreads();
    if (t < 128) {
#pragma unroll
        for (int m = 0; m < ROWS; m++) acc[m] = fmaxf(acc[m], sc[m][c]);
    }
}

// ---------------------------------------------------------------
// embed: h = trop_mm(patchify(x), embed_W) + pos ; g_mx = rowmax(h)
// grid 392, block 256 (4 rows/block)
// ---------------------------------------------------------------
__global__ void embed_kernel(const float* __restrict__ x, const float* __restrict__ W,
                             const float* __restrict__ pos) {
    __shared__ float sx[4][68];
    __shared__ float sw[128][68];
    __shared__ float sc[4][128];
    __shared__ float red[4][4];
    int t = threadIdx.x, m0 = blockIdx.x * 4;
    float acc[4];
    XPatch xl{x, m0};
    trop_core<4, PD>(xl, W, acc, sx, sw);
    combine<4>(acc, sc);
    if (t < 128) {
        int warp = t >> 5, lane = t & 31;
#pragma unroll
        for (int m = 0; m < 4; m++) {
            acc[m] += pos[((m0 + m) % NN) * DD + t];
            g_h[(m0 + m) * DD + t] = acc[m];
            float v = acc[m];
#pragma unroll
            for (int o = 16; o; o >>= 1) v = fmaxf(v, __shfl_xor_sync(~0u, v, o));
            if (lane == 0) red[warp][m] = v;
        }
    }
    __syncthreads();
    if (t < 4)
        g_mx[m0 + t] = fmaxf(fmaxf(red[0][t], red[1][t]),
                             fmaxf(red[2][t], red[3][t]));
}

// ---------------------------------------------------------------
// qkv: {q,k,v} = trop_mm(h, W) - mx
// grid (196,3), block 256 (8 rows/block)
// ---------------------------------------------------------------
__global__ void qkv_kernel(const float* __restrict__ qW, const float* __restrict__ kW,
                           const float* __restrict__ vW) {
    __shared__ float sx[8][68];
    __shared__ float sw[128][68];
    __shared__ float sc[8][128];
    int t = threadIdx.x, m0 = blockIdx.x * 8;
    const float* W = (blockIdx.y == 0) ? qW : (blockIdx.y == 1) ? kW : vW;
    float* O = (blockIdx.y == 0) ? g_q : (blockIdx.y == 1) ? g_k : g_v;
    float acc[8];
    XRow xl{g_h, m0, DD};
    trop_core<8, DD>(xl, W, acc, sx, sw);
    combine<8>(acc, sc);
    if (t < 128) {
#pragma unroll
        for (int m = 0; m < 8; m++)
            O[(m0 + m) * DD + t] = acc[m] - g_mx[m0 + m];
    }
}

// ---------------------------------------------------------------
// fused attention + residual + rowmax epilogue
// grid (25, 8), block 256 = 8 i-rows x 32 lanes (4 d each)
// ---------------------------------------------------------------
__global__ void attn_kernel() {
    __shared__ float ks[8][128];
    __shared__ float vs[8][128];
    int t = threadIdx.x;
    int b = blockIdx.y;
    int il = t >> 5, lane = t & 31;
    int d0 = lane * 4;
    int i = blockIdx.x * 8 + il;
    bool iv = (i < NN);

    const float* qp = g_q + (b * NN + (iv ? i : 0)) * DD + d0;
    float q0 = iv ? qp[0] : NEG, q1 = iv ? qp[1] : NEG;
    float q2 = iv ? qp[2] : NEG, q3 = iv ? qp[3] : NEG;
    float U0 = NEG, U1 = NEG, U2 = NEG, U3 = NEG;

    for (int j0 = 0; j0 < NN; j0 += 8) {
        int j = j0 + il;
        if (j < NN) {
            const float* kp_ = g_k + (b * NN + j) * DD + d0;
            const float* vp_ = g_v + (b * NN + j) * DD + d0;
            *(float4*)&ks[il][d0] = *(const float4*)&kp_[0];
            *(float4*)&vs[il][d0] = *(const float4*)&vp_[0];
        } else {
            float4 nv = make_float4(NEG, NEG, NEG, NEG);
            *(float4*)&ks[il][d0] = nv;
            *(float4*)&vs[il][d0] = nv;
        }
        __syncthreads();
#pragma unroll
        for (int jj = 0; jj < 8; jj++) {
            float4 kv = *(const float4*)&ks[jj][d0];
            float s = fmaxf(fmaxf(q0 + kv.x, q1 + kv.y),
                            fmaxf(q2 + kv.z, q3 + kv.w));
#pragma unroll
            for (int o = 16; o; o >>= 1) s = fmaxf(s, __shfl_xor_sync(~0u, s, o));
            float4 vv = *(const float4*)&vs[jj][d0];
            U0 = fmaxf(U0, s + vv.x); U1 = fmaxf(U1, s + vv.y);
            U2 = fmaxf(U2, s + vv.z); U3 = fmaxf(U3, s + vv.w);
        }
        __syncthreads();
    }

    float um = fmaxf(fmaxf(U0, U1), fmaxf(U2, U3));
#pragma unroll
    for (int o = 16; o; o >>= 1) um = fmaxf(um, __shfl_xor_sync(~0u, um, o));

    if (iv) {
        float* hp = g_h + (b * NN + i) * DD + d0;
        float h0 = fmaxf(hp[0], U0 - um), h1 = fmaxf(hp[1], U1 - um);
        float h2 = fmaxf(hp[2], U2 - um), h3 = fmaxf(hp[3], U3 - um);
        hp[0] = h0; hp[1] = h1; hp[2] = h2; hp[3] = h3;
        float v = fmaxf(fmaxf(h0, h1), fmaxf(h2, h3));
#pragma unroll
        for (int o = 16; o; o >>= 1) v = fmaxf(v, __shfl_xor_sync(~0u, v, o));
        if (lane == 0) g_mx[b * NN + i] = v;
    }
}

// ---------------------------------------------------------------
// ff1: t = max(trop_mm(h, f1W) - mx, tau)
// grid (196, 2), block 256 (8 rows/block)
// ---------------------------------------------------------------
__global__ void ff1_kernel(const float* __restrict__ W, const float* __restrict__ tau) {
    __shared__ float sx[8][68];
    __shared__ float sw[128][68];
    __shared__ float sc[8][128];
    int t = threadIdx.x, m0 = blockIdx.x * 8;
    float acc[8];
    XRow xl{g_h, m0, DD};
    trop_core<8, DD>(xl, W + blockIdx.y * 128 * DD, acc, sx, sw);
    combine<8>(acc, sc);
    if (t < 128) {
        float tv = tau[0];
#pragma unroll
        for (int m = 0; m < 8; m++)
            g_t[(m0 + m) * DFF + blockIdx.y * 128 + t] =
                fmaxf(acc[m] - g_mx[m0 + m], tv);
    }
}

// ---------------------------------------------------------------
// ff2: u = trop_mm(t, f2W); h = max(h, u - rowmax(u)); g_mx = rowmax(h)
// grid 392, block 256 (4 rows/block)
// ---------------------------------------------------------------
__global__ void ff2_kernel(const float* __restrict__ W) {
    __shared__ float sx[4][68];
    __shared__ float sw[128][68];
    __shared__ float sc[4][128];
    __shared__ float red[4][4];
    int t = threadIdx.x, m0 = blockIdx.x * 4;
    float acc[4];
    XRow xl{g_t, m0, DFF};
    trop_core<4, DFF>(xl, W, acc, sx, sw);
    combine<4>(acc, sc);

    int warp = t >> 5, lane = t & 31;
    if (t < 128) {
#pragma unroll
        for (int m = 0; m < 4; m++) {
            float v = acc[m];
#pragma unroll
            for (int o = 16; o; o >>= 1) v = fmaxf(v, __shfl_xor_sync(~0u, v, o));
            if (lane == 0) red[warp][m] = v;
        }
    }
    __syncthreads();
    float hn[4];
    if (t < 128) {
#pragma unroll
        for (int m = 0; m < 4; m++) {
            float rm = fmaxf(fmaxf(red[0][m], red[1][m]),
                             fmaxf(red[2][m], red[3][m]));
            hn[m] = fmaxf(g_h[(m0 + m) * DD + t], acc[m] - rm);
            g_h[(m0 + m) * DD + t] = hn[m];
        }
    }
    __syncthreads();
    if (t < 128) {
#pragma unroll
        for (int m = 0; m < 4; m++) {
            float v = hn[m];
#pragma unroll
            for (int o = 16; o; o >>= 1) v = fmaxf(v, __shfl_xor_sync(~0u, v, o));
            if (lane == 0) red[warp][m] = v;
        }
    }
    __syncthreads();
    if (t < 4)
        g_mx[m0 + t] = fmaxf(fmaxf(red[0][t], red[1][t]),
                             fmaxf(red[2][t], red[3][t]));
}

// ---------------------------------------------------------------
// head with fused tropical global pool
// grid (8, 63), block 128 = 16 c-rows x 8 lanes (16 d each)
// ---------------------------------------------------------------
__global__ void head_kernel(const float* __restrict__ W, const float* __restrict__ ls,
                            float* __restrict__ out) {
    __shared__ float sp[128];
    int t = threadIdx.x, b = blockIdx.x;
    const float* hp = g_h + b * NN * DD + t;
    float v0 = NEG, v1 = NEG, v2 = NEG, v3 = NEG;
    for (int n = 0; n < NN; n += 4) {
        v0 = fmaxf(v0, hp[n * DD]);
        v1 = fmaxf(v1, hp[(n + 1) * DD]);
        v2 = fmaxf(v2, hp[(n + 2) * DD]);
        v3 = fmaxf(v3, hp[(n + 3) * DD]);
    }
    sp[t] = fmaxf(fmaxf(v0, v1), fmaxf(v2, v3));
    __syncthreads();

    int c = blockIdx.y * 16 + (t >> 3);
    int dp = (t & 7) * 16;
    float acc = NEG;
    if (c < CC) {
        const float* w = W + c * DD + dp;
#pragma unroll
        for (int d = 0; d < 16; d += 4) {
            float4 wv = *(const float4*)&w[d];
            acc = fmaxf(acc, fmaxf(fmaxf(sp[dp + d] + wv.x, sp[dp + d + 1] + wv.y),
                                   fmaxf(sp[dp + d + 2] + wv.z, sp[dp + d + 3] + wv.w)));
        }
    }
#pragma unroll
    for (int o = 4; o; o >>= 1) acc = fmaxf(acc, __shfl_xor_sync(~0u, acc, o));
    if ((t & 7) == 0 && c < CC) out[b * CC + c] = acc * ls[0];
}

// ---------------------------------------------------------------
extern "C" void kernel_launch(void* const* d_in, const int* in_sizes, int n_in,
                              void* d_out, int out_size) {
    const float* x      = (const float*)d_in[0];
    const float* embedW = (const float*)d_in[1];
    const float* pos    = (const float*)d_in[2];
    const float* qW[2]  = {(const float*)d_in[3],  (const float*)d_in[9]};
    const float* kW[2]  = {(const float*)d_in[4],  (const float*)d_in[10]};
    const float* vW[2]  = {(const float*)d_in[5],  (const float*)d_in[11]};
    const float* f1W[2] = {(const float*)d_in[6],  (const float*)d_in[12]};
    const float* f2W[2] = {(const float*)d_in[7],  (const float*)d_in[13]};
    const float* tau[2] = {(const float*)d_in[8],  (const float*)d_in[14]};
    const float* headW  = (const float*)d_in[15];
    const float* ls     = (const float*)d_in[16];
    float* out = (float*)d_out;

    embed_kernel<<<MM / 4, 256>>>(x, embedW, pos);

    for (int l = 0; l < 2; l++) {
        qkv_kernel<<<dim3(MM / 8, 3), 256>>>(qW[l], kW[l], vW[l]);
        attn_kernel<<<dim3(25, BB), 256>>>();
        ff1_kernel<<<dim3(MM / 8, 2), 256>>>(f1W[l], tau[l]);
        ff2_kernel<<<MM / 4, 256>>>(f2W[l]);
    }

    head_kernel<<<dim3(BB, 63), 128>>>(headW, ls, out);
}

// round 7
// speedup vs baseline: 1.6559x; 1.0281x over previous
#include <cuda_runtime.h>

#define NEG (-1e30f)

// dims
#define BB   8
#define NN   196
#define DD   128
#define DFF  256
#define PD   256
#define MM   (BB*NN)   // 1568
#define CC   1000

// -------- scratch (device globals; no allocation allowed) --------
__device__ __align__(128) float g_h[MM * DD];
__device__ __align__(128) float g_q[MM * DD];
__device__ __align__(128) float g_k[MM * DD];
__device__ __align__(128) float g_v[MM * DD];
__device__ __align__(128) float g_t[MM * DFF];
__device__ __align__(128) float g_mx[MM];

// -------- Blackwell packed helpers --------
__device__ __forceinline__ float fmax3(float a, float b, float c) {
    float d;
    asm("max.f32 %0, %1, %2, %3;" : "=f"(d) : "f"(a), "f"(b), "f"(c));
    return d;
}
__device__ __forceinline__ unsigned long long addx2(unsigned long long a,
                                                    unsigned long long b) {
    unsigned long long r;
    asm("add.rn.f32x2 %0, %1, %2;" : "=l"(r) : "l"(a), "l"(b));
    return r;
}
__device__ __forceinline__ void unpk(float& lo, float& hi, unsigned long long v) {
    asm("mov.b64 {%0, %1}, %2;" : "=f"(lo), "=f"(hi) : "l"(v));
}
__device__ __forceinline__ unsigned long long pk(float lo, float hi) {
    unsigned long long v;
    asm("mov.b64 %0, {%1, %2};" : "=l"(v) : "f"(lo), "f"(hi));
    return v;
}

// ---------------------------------------------------------------
// X-tile loaders (stage ROWS x 64 k-chunk into shared, t < ROWS*16)
// ---------------------------------------------------------------
struct XRow {
    const float* X; int m0; int ld;
    __device__ __forceinline__ void operator()(float (*sx)[68], int k0, int t) const {
        int row = t >> 4, kp = (t & 15) * 4;
        *(float4*)&sx[row][kp] = *(const float4*)&X[(m0 + row) * ld + k0 + kp];
    }
};
// patchify-on-the-fly: x is (8,224,224); row m -> (b,n); k index j -> (py,px)
struct XPatch {
    const float* x; int m0;
    __device__ __forceinline__ void operator()(float (*sx)[68], int k0, int t) const {
        int row = t >> 4, kp = (t & 15) * 4;
        int m = m0 + row;
        int b = m / NN, n = m % NN;
        int gy = n / 14, gx = n % 14;
        int j = k0 + kp;
        int py = j >> 4, px = j & 15;
        *(float4*)&sx[row][kp] =
            *(const float4*)&x[(b * 224 + gy * 16 + py) * 224 + gx * 16 + px];
    }
};

// ---------------------------------------------------------------
// K-split tropical GEMM core. Block = 256 threads: col c = t&127,
// K-group g = t>>7 handles kk in [g*32, g*32+32) of each 64-chunk.
// Inner loop: packed f32x2 adds + 3-input max (FMNMX3).
// ---------------------------------------------------------------
template<int ROWS, int K, class XL>
__device__ __forceinline__ void trop_core(const XL& xl, const float* __restrict__ W,
                                          float acc[ROWS],
                                          float (*sx)[68], float (*sw)[68])
{
    int t = threadIdx.x;
    int c = t & 127, kbase = (t >> 7) * 32;
#pragma unroll
    for (int m = 0; m < ROWS; m++) acc[m] = NEG;

    for (int k0 = 0; k0 < K; k0 += 64) {
        if (t < ROWS * 16) xl(sx, k0, t);
#pragma unroll
        for (int p = 0; p < 8; p++) {        // 128 rows x 16 float4 / 256 thr
            int l = p * 256 + t;
            int i = l >> 4, kp = (l & 15) * 4;
            *(float4*)&sw[i][kp] = *(const float4*)&W[i * K + k0 + kp];
        }
        __syncthreads();
#pragma unroll
        for (int kk = 0; kk < 32; kk += 4) {
            ulonglong2 wv = *(const ulonglong2*)&sw[c][kbase + kk];
#pragma unroll
            for (int m = 0; m < ROWS; m++) {
                ulonglong2 xv = *(const ulonglong2*)&sx[m][kbase + kk]; // broadcast
                unsigned long long s01 = addx2(xv.x, wv.x);
                unsigned long long s23 = addx2(xv.y, wv.y);
                float s0, s1, s2, s3;
                unpk(s0, s1, s01);
                unpk(s2, s3, s23);
                acc[m] = fmax3(acc[m], s0, s1);
                acc[m] = fmax3(acc[m], s2, s3);
            }
        }
        __syncthreads();
    }
}

// combine the two K-groups: after this, group 0 (t<128) holds the result
template<int ROWS>
__device__ __forceinline__ void combine(float acc[ROWS], float (*sc)[128]) {
    int t = threadIdx.x, c = t & 127;
    if (t >= 128) {
#pragma unroll
        for (int m = 0; m < ROWS; m++) sc[m][c] = acc[m];
    }
    __syncthreads();
    if (t < 128) {
#pragma unroll
        for (int m = 0; m < ROWS; m++) acc[m] = fmaxf(acc[m], sc[m][c]);
    }
}

// ---------------------------------------------------------------
// embed: h = trop_mm(patchify(x), embed_W) + pos ; g_mx = rowmax(h)
// grid 392, block 256 (4 rows/block)
// ---------------------------------------------------------------
__global__ void embed_kernel(const float* __restrict__ x, const float* __restrict__ W,
                             const float* __restrict__ pos) {
    __shared__ float sx[4][68];
    __shared__ float sw[128][68];
    __shared__ float sc[4][128];
    __shared__ float red[4][4];
    int t = threadIdx.x, m0 = blockIdx.x * 4;
    float acc[4];
    XPatch xl{x, m0};
    trop_core<4, PD>(xl, W, acc, sx, sw);
    combine<4>(acc, sc);
    if (t < 128) {
        int warp = t >> 5, lane = t & 31;
#pragma unroll
        for (int m = 0; m < 4; m++) {
            acc[m] += pos[((m0 + m) % NN) * DD + t];
            g_h[(m0 + m) * DD + t] = acc[m];
            float v = acc[m];
#pragma unroll
            for (int o = 16; o; o >>= 1) v = fmaxf(v, __shfl_xor_sync(~0u, v, o));
            if (lane == 0) red[warp][m] = v;
        }
    }
    __syncthreads();
    if (t < 4)
        g_mx[m0 + t] = fmax3(fmaxf(red[0][t], red[1][t]), red[2][t], red[3][t]);
}

// ---------------------------------------------------------------
// qkv: {q,k,v} = trop_mm(h, W) - mx
// grid (196,3), block 256 (8 rows/block)
// ---------------------------------------------------------------
__global__ void qkv_kernel(const float* __restrict__ qW, const float* __restrict__ kW,
                           const float* __restrict__ vW) {
    __shared__ float sx[8][68];
    __shared__ float sw[128][68];
    __shared__ float sc[8][128];
    int t = threadIdx.x, m0 = blockIdx.x * 8;
    const float* W = (blockIdx.y == 0) ? qW : (blockIdx.y == 1) ? kW : vW;
    float* O = (blockIdx.y == 0) ? g_q : (blockIdx.y == 1) ? g_k : g_v;
    float acc[8];
    XRow xl{g_h, m0, DD};
    trop_core<8, DD>(xl, W, acc, sx, sw);
    combine<8>(acc, sc);
    if (t < 128) {
#pragma unroll
        for (int m = 0; m < 8; m++)
            O[(m0 + m) * DD + t] = acc[m] - g_mx[m0 + m];
    }
}

// ---------------------------------------------------------------
// fused attention + residual + rowmax epilogue
// grid (25, 8), block 256 = 8 i-rows x 32 lanes (4 d each)
// ---------------------------------------------------------------
__global__ void attn_kernel() {
    __shared__ float ks[8][128];
    __shared__ float vs[8][128];
    int t = threadIdx.x;
    int b = blockIdx.y;
    int il = t >> 5, lane = t & 31;
    int d0 = lane * 4;
    int i = blockIdx.x * 8 + il;
    bool iv = (i < NN);

    const float* qp = g_q + (b * NN + (iv ? i : 0)) * DD + d0;
    float q0 = iv ? qp[0] : NEG, q1 = iv ? qp[1] : NEG;
    float q2 = iv ? qp[2] : NEG, q3 = iv ? qp[3] : NEG;
    unsigned long long Q01 = pk(q0, q1), Q23 = pk(q2, q3);
    float U0 = NEG, U1 = NEG, U2 = NEG, U3 = NEG;

    for (int j0 = 0; j0 < NN; j0 += 8) {
        int j = j0 + il;
        if (j < NN) {
            const float* kp_ = g_k + (b * NN + j) * DD + d0;
            const float* vp_ = g_v + (b * NN + j) * DD + d0;
            *(float4*)&ks[il][d0] = *(const float4*)&kp_[0];
            *(float4*)&vs[il][d0] = *(const float4*)&vp_[0];
        } else {
            float4 nv = make_float4(NEG, NEG, NEG, NEG);
            *(float4*)&ks[il][d0] = nv;
            *(float4*)&vs[il][d0] = nv;
        }
        __syncthreads();
#pragma unroll
        for (int jj = 0; jj < 8; jj++) {
            ulonglong2 kv = *(const ulonglong2*)&ks[jj][d0];
            float s0, s1, s2, s3;
            unpk(s0, s1, addx2(Q01, kv.x));
            unpk(s2, s3, addx2(Q23, kv.y));
            float s = fmaxf(fmax3(s0, s1, s2), s3);
#pragma unroll
            for (int o = 16; o; o >>= 1) s = fmaxf(s, __shfl_xor_sync(~0u, s, o));
            ulonglong2 vv = *(const ulonglong2*)&vs[jj][d0];
            unsigned long long S2 = pk(s, s);
            float a0, a1, a2, a3;
            unpk(a0, a1, addx2(S2, vv.x));
            unpk(a2, a3, addx2(S2, vv.y));
            U0 = fmaxf(U0, a0); U1 = fmaxf(U1, a1);
            U2 = fmaxf(U2, a2); U3 = fmaxf(U3, a3);
        }
        __syncthreads();
    }

    float um = fmax3(fmaxf(U0, U1), U2, U3);
#pragma unroll
    for (int o = 16; o; o >>= 1) um = fmaxf(um, __shfl_xor_sync(~0u, um, o));

    if (iv) {
        float* hp = g_h + (b * NN + i) * DD + d0;
        float h0 = fmaxf(hp[0], U0 - um), h1 = fmaxf(hp[1], U1 - um);
        float h2 = fmaxf(hp[2], U2 - um), h3 = fmaxf(hp[3], U3 - um);
        hp[0] = h0; hp[1] = h1; hp[2] = h2; hp[3] = h3;
        float v = fmax3(fmaxf(h0, h1), h2, h3);
#pragma unroll
        for (int o = 16; o; o >>= 1) v = fmaxf(v, __shfl_xor_sync(~0u, v, o));
        if (lane == 0) g_mx[b * NN + i] = v;
    }
}

// ---------------------------------------------------------------
// ff1: t = max(trop_mm(h, f1W) - mx, tau)
// grid (196, 2), block 256 (8 rows/block)
// ---------------------------------------------------------------
__global__ void ff1_kernel(const float* __restrict__ W, const float* __restrict__ tau) {
    __shared__ float sx[8][68];
    __shared__ float sw[128][68];
    __shared__ float sc[8][128];
    int t = threadIdx.x, m0 = blockIdx.x * 8;
    float acc[8];
    XRow xl{g_h, m0, DD};
    trop_core<8, DD>(xl, W + blockIdx.y * 128 * DD, acc, sx, sw);
    combine<8>(acc, sc);
    if (t < 128) {
        float tv = tau[0];
#pragma unroll
        for (int m = 0; m < 8; m++)
            g_t[(m0 + m) * DFF + blockIdx.y * 128 + t] =
                fmaxf(acc[m] - g_mx[m0 + m], tv);
    }
}

// ---------------------------------------------------------------
// ff2: u = trop_mm(t, f2W); h = max(h, u - rowmax(u)); g_mx = rowmax(h)
// grid 392, block 256 (4 rows/block)
// ---------------------------------------------------------------
__global__ void ff2_kernel(const float* __restrict__ W) {
    __shared__ float sx[4][68];
    __shared__ float sw[128][68];
    __shared__ float sc[4][128];
    __shared__ float red[4][4];
    int t = threadIdx.x, m0 = blockIdx.x * 4;
    float acc[4];
    XRow xl{g_t, m0, DFF};
    trop_core<4, DFF>(xl, W, acc, sx, sw);
    combine<4>(acc, sc);

    int warp = t >> 5, lane = t & 31;
    if (t < 128) {
#pragma unroll
        for (int m = 0; m < 4; m++) {
            float v = acc[m];
#pragma unroll
            for (int o = 16; o; o >>= 1) v = fmaxf(v, __shfl_xor_sync(~0u, v, o));
            if (lane == 0) red[warp][m] = v;
        }
    }
    __syncthreads();
    float hn[4];
    if (t < 128) {
#pragma unroll
        for (int m = 0; m < 4; m++) {
            float rm = fmax3(fmaxf(red[0][m], red[1][m]), red[2][m], red[3][m]);
            hn[m] = fmaxf(g_h[(m0 + m) * DD + t], acc[m] - rm);
            g_h[(m0 + m) * DD + t] = hn[m];
        }
    }
    __syncthreads();
    if (t < 128) {
#pragma unroll
        for (int m = 0; m < 4; m++) {
            float v = hn[m];
#pragma unroll
            for (int o = 16; o; o >>= 1) v = fmaxf(v, __shfl_xor_sync(~0u, v, o));
            if (lane == 0) red[warp][m] = v;
        }
    }
    __syncthreads();
    if (t < 4)
        g_mx[m0 + t] = fmax3(fmaxf(red[0][t], red[1][t]), red[2][t], red[3][t]);
}

// ---------------------------------------------------------------
// head with fused tropical global pool
// grid (8, 63), block 128 = 16 c-rows x 8 lanes (16 d each)
// ---------------------------------------------------------------
__global__ void head_kernel(const float* __restrict__ W, const float* __restrict__ ls,
                            float* __restrict__ out) {
    __shared__ float sp[128];
    int t = threadIdx.x, b = blockIdx.x;
    const float* hp = g_h + b * NN * DD + t;
    float v0 = NEG, v1 = NEG, v2 = NEG, v3 = NEG;
    for (int n = 0; n < NN; n += 4) {
        v0 = fmaxf(v0, hp[n * DD]);
        v1 = fmaxf(v1, hp[(n + 1) * DD]);
        v2 = fmaxf(v2, hp[(n + 2) * DD]);
        v3 = fmaxf(v3, hp[(n + 3) * DD]);
    }
    sp[t] = fmax3(fmaxf(v0, v1), v2, v3);
    __syncthreads();

    int c = blockIdx.y * 16 + (t >> 3);
    int dp = (t & 7) * 16;
    float acc = NEG;
    if (c < CC) {
        const float* w = W + c * DD + dp;
#pragma unroll
        for (int d = 0; d < 16; d += 4) {
            float4 wv = *(const float4*)&w[d];
            acc = fmax3(acc, fmaxf(sp[dp + d] + wv.x, sp[dp + d + 1] + wv.y),
                        fmaxf(sp[dp + d + 2] + wv.z, sp[dp + d + 3] + wv.w));
        }
    }
#pragma unroll
    for (int o = 4; o; o >>= 1) acc = fmaxf(acc, __shfl_xor_sync(~0u, acc, o));
    if ((t & 7) == 0 && c < CC) out[b * CC + c] = acc * ls[0];
}

// ---------------------------------------------------------------
extern "C" void kernel_launch(void* const* d_in, const int* in_sizes, int n_in,
                              void* d_out, int out_size) {
    const float* x      = (const float*)d_in[0];
    const float* embedW = (const float*)d_in[1];
    const float* pos    = (const float*)d_in[2];
    const float* qW[2]  = {(const float*)d_in[3],  (const float*)d_in[9]};
    const float* kW[2]  = {(const float*)d_in[4],  (const float*)d_in[10]};
    const float* vW[2]  = {(const float*)d_in[5],  (const float*)d_in[11]};
    const float* f1W[2] = {(const float*)d_in[6],  (const float*)d_in[12]};
    const float* f2W[2] = {(const float*)d_in[7],  (const float*)d_in[13]};
    const float* tau[2] = {(const float*)d_in[8],  (const float*)d_in[14]};
    const float* headW  = (const float*)d_in[15];
    const float* ls     = (const float*)d_in[16];
    float* out = (float*)d_out;

    embed_kernel<<<MM / 4, 256>>>(x, embedW, pos);

    for (int l = 0; l < 2; l++) {
        qkv_kernel<<<dim3(MM / 8, 3), 256>>>(qW[l], kW[l], vW[l]);
        attn_kernel<<<dim3(25, BB), 256>>>();
        ff1_kernel<<<dim3(MM / 8, 2), 256>>>(f1W[l], tau[l]);
        ff2_kernel<<<MM / 4, 256>>>(f2W[l]);
    }

    head_kernel<<<dim3(BB, 63), 128>>>(headW, ls, out);
}